// round 1
// baseline (speedup 1.0000x reference)
#include <cuda_runtime.h>
#include <math.h>

// Problem constants (match reference)
#define NB 4
#define NC 200
#define NG 32
#define NN 32256
#define GX 256   // blocks per batch in x

// Global accumulators: ce, seg, iou sums (double) + positive count.
// Zero-initialized at module load; finalize() resets them after every launch,
// so kernel_launch is deterministic under graph replay.
__device__ double g_acc[3];
__device__ unsigned int g_cnt;

// focal term, t = 0 (the overwhelmingly common case)
__device__ __forceinline__ float focal0(float x) {
    float u  = __expf(x);               // e^x
    float s  = 1.f + u;
    float r  = __fdividef(1.f, s);      // sigmoid(-x) = 1-p
    float p  = u * r;                   // sigmoid(x)
    float sp = __logf(s);               // softplus(x)
    return 0.75f * sp * p * p;
}

// focal term, general t in {0,1}
// t=1: 0.25 * softplus(-x) * (1-p)^2, with softplus(-x) = softplus(x) - x
__device__ __forceinline__ float focalg(float x, unsigned t) {
    float u   = __expf(x);
    float s   = 1.f + u;
    float r   = __fdividef(1.f, s);
    float sp  = __logf(s);
    float tf  = (float)t;
    float spt = sp - tf * x;            // softplus(+/-x)
    float w   = r * (t ? 1.f : u);      // t? (1-p) : p
    float alpha = 0.75f - 0.5f * tf;    // t? 0.25 : 0.75
    return alpha * spt * w * w;
}

__global__ void __launch_bounds__(256)
loss_main(const float* __restrict__ logits,        // [B,N,C]
          const float* __restrict__ psegs,         // [B,N,3]
          const float* __restrict__ grids,         // [B,N]
          const float* __restrict__ fps,           // [B]
          const float* __restrict__ gts,           // [B,G,2]
          const int*   __restrict__ glab,          // [B,G]
          const unsigned char* __restrict__ mask)  // [B,N]
{
    const int lane = threadIdx.x & 31;
    const int b    = blockIdx.y;
    const int wid  = blockIdx.x * (blockDim.x >> 5) + (threadIdx.x >> 5);
    const int W    = gridDim.x * (blockDim.x >> 5);

    // lane <-> GT g mapping (G == 32)
    float2 seg  = ((const float2*)gts)[b * NG + lane];
    float s_g   = seg.x, e_g = seg.y;
    float len_g = e_g - s_g;
    int   lbl_g = glab[b * NG + lane];
    // geometric bucket midpoints: mid(l) = 3*fps*sqrt(2)*2^l
    float Cm = 3.f * fps[b] * 1.41421356237309515f;

    float ce_acc = 0.f, seg_acc = 0.f, iou_acc = 0.f;
    int   cnt = 0;

    for (int n = wid; n < NN; n += W) {
        int lvl = (n >= 16384) + (n >= 24576) + (n >= 28672) + (n >= 30720) + (n >= 31744);
        float lo = (lvl == 0) ? 0.f : Cm * exp2f((float)(lvl - 1));
        float hi = (lvl == 5) ? __int_as_float(0x7f800000) : Cm * exp2f((float)lvl);

        long long bn = (long long)b * NN + n;
        float gt     = grids[bn];
        float ps1    = psegs[bn * 3 + 1];
        float ps2    = psegs[bn * 3 + 2];
        float validf = mask[bn] ? 0.f : 1.f;

        bool posg = (len_g >= lo) && (len_g < hi) && (gt > s_g) && (gt < e_g);
        unsigned pm = __ballot_sync(0xffffffffu, posg);
        unsigned nib0 = 0, nib1 = 0;

        if (pm) {
            cnt += (int)posg;
            if (posg) {
                // smooth-L1 on log offsets
                float d1 = ps1 - __logf(gt - s_g);
                float d2 = ps2 - __logf(e_g - gt);
                float a1 = fabsf(d1), a2 = fabsf(d2);
                seg_acc += (a1 < 1.f ? 0.5f * d1 * d1 : a1 - 0.5f)
                         + (a2 < 1.f ? 0.5f * d2 * d2 : a2 - 0.5f);
                // IoU of decoded segment vs GT
                float pls = gt - __expf(ps1);
                float ple = gt + __expf(ps2);
                float inter = fmaxf(fminf(ple, e_g) - fmaxf(pls, s_g), 0.f);
                float uni   = (ple - pls) + len_g - inter;
                iou_acc += 1.f - __fdividef(inter, uni);
            }
            // build this lane's 4-bit class-target nibbles for its two c-quads
            unsigned m = pm;
            while (m) {
                int g2 = __ffs(m) - 1; m &= m - 1;
                int l2 = __shfl_sync(0xffffffffu, lbl_g, g2);
                unsigned d0 = (unsigned)(l2 - 4 * lane);          // quad c = 4*lane..+3
                if (d0 < 4u) nib0 |= 1u << d0;
                unsigned d1i = (unsigned)(l2 - 4 * (lane + 32));  // quad c = 4*(lane+32)..+3
                if (d1i < 4u) nib1 |= 1u << d1i;
            }
        }

        // focal pass: 200 floats = 50 float4 lanes (32 + 18)
        const float4* row = (const float4*)(logits + bn * NC);
        float4 v0 = row[lane];
        float ce_l;
        if (pm == 0) {  // warp-uniform: every class target is 0
            ce_l = focal0(v0.x) + focal0(v0.y) + focal0(v0.z) + focal0(v0.w);
            if (lane < 18) {
                float4 v1 = row[lane + 32];
                ce_l += focal0(v1.x) + focal0(v1.y) + focal0(v1.z) + focal0(v1.w);
            }
        } else {
            ce_l = focalg(v0.x,  nib0        & 1u) + focalg(v0.y, (nib0 >> 1) & 1u)
                 + focalg(v0.z, (nib0 >> 2)  & 1u) + focalg(v0.w, (nib0 >> 3) & 1u);
            if (lane < 18) {
                float4 v1 = row[lane + 32];
                ce_l += focalg(v1.x,  nib1        & 1u) + focalg(v1.y, (nib1 >> 1) & 1u)
                      + focalg(v1.z, (nib1 >> 2)  & 1u) + focalg(v1.w, (nib1 >> 3) & 1u);
            }
        }
        ce_acc += validf * ce_l;
    }

    // warp reduction
    #pragma unroll
    for (int o = 16; o; o >>= 1) {
        ce_acc  += __shfl_xor_sync(0xffffffffu, ce_acc,  o);
        seg_acc += __shfl_xor_sync(0xffffffffu, seg_acc, o);
        iou_acc += __shfl_xor_sync(0xffffffffu, iou_acc, o);
        cnt     += __shfl_xor_sync(0xffffffffu, cnt,     o);
    }
    if (lane == 0) {
        atomicAdd(&g_acc[0], (double)ce_acc);
        atomicAdd(&g_acc[1], (double)seg_acc);
        atomicAdd(&g_acc[2], (double)iou_acc);
        atomicAdd(&g_cnt, (unsigned)cnt);
    }
}

__global__ void finalize_kernel(float* __restrict__ out) {
    double np = (double)g_cnt;
    if (np < 1.0) np = 1.0;
    out[0] = (float)(g_acc[0] / np);
    out[1] = (float)(g_acc[1] / np);
    out[2] = (float)(g_acc[2] / np);
    // reset for next (graph-replayed) launch
    g_acc[0] = 0.0; g_acc[1] = 0.0; g_acc[2] = 0.0;
    g_cnt = 0u;
}

extern "C" void kernel_launch(void* const* d_in, const int* in_sizes, int n_in,
                              void* d_out, int out_size) {
    const float*         logits = (const float*)d_in[0];
    const float*         psegs  = (const float*)d_in[1];
    const float*         grids  = (const float*)d_in[2];
    const float*         fps    = (const float*)d_in[3];
    const float*         gts    = (const float*)d_in[4];
    const int*           glab   = (const int*)d_in[5];
    const unsigned char* maskp  = (const unsigned char*)d_in[6];
    float* out = (float*)d_out;

    dim3 grid(GX, NB);
    loss_main<<<grid, 256>>>(logits, psegs, grids, fps, gts, glab, maskp);
    finalize_kernel<<<1, 1>>>(out);
    (void)in_sizes; (void)n_in; (void)out_size;
}

// round 3
// speedup vs baseline: 1.8985x; 1.8985x over previous
#include <cuda_runtime.h>

#define NB 4
#define NC 200
#define NG 32
#define NN 32256
#define CH 64                     // anchors per block
#define NBX (NN / CH)             // 504
#define TOTAL_BLOCKS (NB * NBX)   // 2016

// Global accumulators (zero at module load; last block resets after use,
// so every graph replay sees zeros -> deterministic).
__device__ double g_acc[3];
__device__ unsigned g_cnt;
__device__ unsigned g_done;

// t=0 focal core in log2 units: returns lg2(1+e^x) * sigmoid(x)^2.
// Caller multiplies by valid * 0.75 * ln2.
__device__ __forceinline__ float g0(float x) {
    float u = __expf(x);              // FMUL + EX2
    float s = 1.f + u;
    float r = __fdividef(1.f, s);     // RCP  (sigmoid(-x))
    float lg = __log2f(s);            // LG2
    float w = 1.f - r;                // sigmoid(x)
    return lg * w * w;
}

__global__ void __launch_bounds__(256)
loss_fused(const float* __restrict__ logits,        // [B,N,C]
           const float* __restrict__ psegs,         // [B,N,3]
           const float* __restrict__ grids,         // [B,N]
           const float* __restrict__ fps,           // [B]
           const float* __restrict__ gts,           // [B,G,2]
           const int*   __restrict__ glab,          // [B,G]
           const unsigned char* __restrict__ mask,  // [B,N]
           float* __restrict__ out)                 // [3]
{
    __shared__ unsigned s_tgt[CH * 8];   // 224-bit class-target mask per anchor
    __shared__ float    s_w[CH];         // valid * 0.75 * ln2
    __shared__ float    s_v[CH];         // valid
    __shared__ float    s_red[3 * 8];
    __shared__ int      s_redc[8];

    const int tid  = threadIdx.x;
    const int lane = tid & 31;
    const int warp = tid >> 5;
    const int b    = blockIdx.y;
    const int n0   = blockIdx.x * CH;

    s_tgt[tid] = 0u;
    s_tgt[tid + 256] = 0u;
    __syncthreads();

    // ---------------- Phase A: matching + seg/IoU + target masks ----------
    // lane g <-> GT g (G == 32). All level boundaries are multiples of CH,
    // so the level is uniform across the block.
    float2 seg  = ((const float2*)gts)[b * NG + lane];
    float s_g   = seg.x, e_g = seg.y;
    float len_g = e_g - s_g;
    int   lbl   = glab[b * NG + lane];
    float Cm    = 3.0f * fps[b] * 1.41421356237309515f;  // 3*fps*sqrt(2)

    int lvl = (n0 >= 16384) + (n0 >= 24576) + (n0 >= 28672) + (n0 >= 30720) + (n0 >= 31744);
    float lo = (lvl == 0) ? 0.f : Cm * exp2f((float)(lvl - 1));
    float hi = (lvl == 5) ? __int_as_float(0x7f800000) : Cm * exp2f((float)lvl);
    bool inb = (len_g >= lo) && (len_g < hi);

    float ce_acc = 0.f, seg_acc = 0.f, iou_acc = 0.f;
    int cnt = 0;

    for (int i = 0; i < 8; ++i) {
        int a = warp * 8 + i;
        long long bn = (long long)b * NN + n0 + a;
        float gv  = grids[bn];
        float ps1 = psegs[bn * 3 + 1];
        float ps2 = psegs[bn * 3 + 2];
        if (lane == 0) {
            float vf = mask[bn] ? 0.f : 1.f;
            s_v[a] = vf;
            s_w[a] = vf * (0.75f * 0.69314718055994531f);
        }
        bool pos = inb && (gv > s_g) && (gv < e_g);
        if (pos) {
            cnt++;
            // smooth-L1 on log offsets (offsets strictly positive here)
            float d1 = ps1 - __logf(gv - s_g);
            float d2 = ps2 - __logf(e_g - gv);
            float a1 = fabsf(d1), a2 = fabsf(d2);
            seg_acc += (a1 < 1.f ? 0.5f * d1 * d1 : a1 - 0.5f)
                     + (a2 < 1.f ? 0.5f * d2 * d2 : a2 - 0.5f);
            // IoU of decoded segment vs GT
            float pls = gv - __expf(ps1);
            float ple = gv + __expf(ps2);
            float inter = fmaxf(fminf(ple, e_g) - fmaxf(pls, s_g), 0.f);
            float uni   = (ple - pls) + len_g - inter;
            iou_acc += 1.f - __fdividef(inter, uni);
            // union of matched classes (dedup via OR)
            atomicOr(&s_tgt[a * 8 + (lbl >> 5)], 1u << (lbl & 31));
        }
    }
    __syncthreads();

    // ---------------- Phase B: dense t=0 focal streaming ------------------
    // Block covers 64 contiguous anchor rows of 200 floats = 3200 float4,
    // flattened: quad q -> base[q]; anchor = q/50.
    // Two rotating accumulators keep independent FADD chains.
    const float4* basep = (const float4*)(logits + ((size_t)b * NN + n0) * NC);
    float ceB0 = 0.f, ceB1 = 0.f;
    for (int q = tid; q < CH * 50; q += 256) {
        int a = q / 50;
        float4 v = basep[q];
        float wA = s_w[a];
        ceB0 += wA * (g0(v.x) + g0(v.z));
        ceB1 += wA * (g0(v.y) + g0(v.w));
    }
    ce_acc += ceB0 + ceB1;

    // ---------------- Phase C: sparse t=1 corrections ----------------------
    // For each set (anchor, class) bit: add fl1 - fl0.
    const float* rowbase = logits + ((size_t)b * NN + n0) * NC;
    for (int wq = tid; wq < CH * 8; wq += 256) {
        unsigned m = s_tgt[wq];
        if (m) {
            int a  = wq >> 3;
            int wi = wq & 7;
            float vf = s_v[a];
            const float* rp = rowbase + a * NC + wi * 32;
            do {
                int bp = __ffs(m) - 1; m &= m - 1;
                float x = rp[bp];
                float u = __expf(x);
                float s = 1.f + u;
                float r = __fdividef(1.f, s);     // 1-p
                float sp = __logf(s);             // softplus(x)
                float w = 1.f - r;                // p
                // fl1 = 0.25*(sp - x)*r^2 ; fl0 = 0.75*sp*w^2
                ce_acc += vf * (0.25f * (sp - x) * r * r - 0.75f * sp * w * w);
            } while (m);
        }
    }

    // ---------------- Reduction + last-block finalize ----------------------
    #pragma unroll
    for (int o = 16; o; o >>= 1) {
        ce_acc  += __shfl_xor_sync(0xffffffffu, ce_acc,  o);
        seg_acc += __shfl_xor_sync(0xffffffffu, seg_acc, o);
        iou_acc += __shfl_xor_sync(0xffffffffu, iou_acc, o);
        cnt     += __shfl_xor_sync(0xffffffffu, cnt,     o);
    }
    if (lane == 0) {
        s_red[warp]      = ce_acc;
        s_red[8 + warp]  = seg_acc;
        s_red[16 + warp] = iou_acc;
        s_redc[warp]     = cnt;
    }
    __syncthreads();
    if (tid == 0) {
        double ce = 0.0, sg = 0.0, io = 0.0; int c = 0;
        #pragma unroll
        for (int w = 0; w < 8; ++w) {
            ce += (double)s_red[w];
            sg += (double)s_red[8 + w];
            io += (double)s_red[16 + w];
            c  += s_redc[w];
        }
        atomicAdd(&g_acc[0], ce);
        atomicAdd(&g_acc[1], sg);
        atomicAdd(&g_acc[2], io);
        atomicAdd(&g_cnt, (unsigned)c);
        __threadfence();
        unsigned t = atomicAdd(&g_done, 1u);
        if (t == TOTAL_BLOCKS - 1) {
            // all other blocks' contributions are visible (fence before ticket)
            double np = (double)atomicAdd(&g_cnt, 0u);
            if (np < 1.0) np = 1.0;
            double a0 = atomicAdd(&g_acc[0], 0.0);
            double a1 = atomicAdd(&g_acc[1], 0.0);
            double a2 = atomicAdd(&g_acc[2], 0.0);
            out[0] = (float)(a0 / np);
            out[1] = (float)(a1 / np);
            out[2] = (float)(a2 / np);
            // reset for next graph replay
            g_acc[0] = 0.0; g_acc[1] = 0.0; g_acc[2] = 0.0;
            g_cnt = 0u; g_done = 0u;
        }
    }
}

extern "C" void kernel_launch(void* const* d_in, const int* in_sizes, int n_in,
                              void* d_out, int out_size) {
    const float*         logits = (const float*)d_in[0];
    const float*         psegs  = (const float*)d_in[1];
    const float*         grids  = (const float*)d_in[2];
    const float*         fps    = (const float*)d_in[3];
    const float*         gts    = (const float*)d_in[4];
    const int*           glab   = (const int*)d_in[5];
    const unsigned char* maskp  = (const unsigned char*)d_in[6];
    float* out = (float*)d_out;

    dim3 grid(NBX, NB);
    loss_fused<<<grid, 256>>>(logits, psegs, grids, fps, gts, glab, maskp, out);
    (void)in_sizes; (void)n_in; (void)out_size;
}

// round 4
// speedup vs baseline: 1.9984x; 1.0526x over previous
#include <cuda_runtime.h>

#define NB 4
#define NC 200
#define NG 32
#define NN 32256
#define CH 128                    // anchors per block
#define NBX (NN / CH)             // 252
#define TOTAL_BLOCKS (NB * NBX)   // 1008 = 7 * 144  -> single wave
#define QPT ((CH * 50) / 256)     // 25 quads per thread in phase B

// Global accumulators (zero at module load; last block resets after use,
// so every graph replay sees zeros -> deterministic).
__device__ double g_acc[3];
__device__ unsigned g_cnt;
__device__ unsigned g_done;

// t=0 focal core in log2 units: returns lg2(1+e^x) * sigmoid(x)^2.
// Caller multiplies by valid * 0.75 * ln2.
__device__ __forceinline__ float g0(float x) {
    float u = __expf(x);              // FMUL + EX2
    float s = 1.f + u;
    float r = __fdividef(1.f, s);     // RCP  (sigmoid(-x))
    float lg = __log2f(s);            // LG2
    float w = 1.f - r;                // sigmoid(x)
    return lg * w * w;
}

__global__ void __launch_bounds__(256, 7)
loss_fused(const float* __restrict__ logits,        // [B,N,C]
           const float* __restrict__ psegs,         // [B,N,3]
           const float* __restrict__ grids,         // [B,N]
           const float* __restrict__ fps,           // [B]
           const float* __restrict__ gts,           // [B,G,2]
           const int*   __restrict__ glab,          // [B,G]
           const unsigned char* __restrict__ mask,  // [B,N]
           float* __restrict__ out)                 // [3]
{
    __shared__ unsigned s_tgt[CH * 8];   // 224-bit class-target mask per anchor
    __shared__ float    s_w[CH];         // valid * 0.75 * ln2
    __shared__ float    s_v[CH];         // valid
    __shared__ float    s_red[3 * 8];
    __shared__ int      s_redc[8];

    const int tid  = threadIdx.x;
    const int lane = tid & 31;
    const int warp = tid >> 5;
    const int b    = blockIdx.y;
    const int n0   = blockIdx.x * CH;

    #pragma unroll
    for (int k = 0; k < 4; ++k) s_tgt[tid + k * 256] = 0u;
    __syncthreads();

    // ---------------- Phase A: matching + seg/IoU + target masks ----------
    // lane g <-> GT g (G == 32). All level boundaries are multiples of CH,
    // so the level is uniform across the block.
    float2 seg  = ((const float2*)gts)[b * NG + lane];
    float s_g   = seg.x, e_g = seg.y;
    float len_g = e_g - s_g;
    int   lbl   = glab[b * NG + lane];
    float Cm    = 3.0f * fps[b] * 1.41421356237309515f;  // 3*fps*sqrt(2)

    int lvl = (n0 >= 16384) + (n0 >= 24576) + (n0 >= 28672) + (n0 >= 30720) + (n0 >= 31744);
    float lo = (lvl == 0) ? 0.f : Cm * exp2f((float)(lvl - 1));
    float hi = (lvl == 5) ? __int_as_float(0x7f800000) : Cm * exp2f((float)lvl);
    bool inb = (len_g >= lo) && (len_g < hi);

    float ce_acc = 0.f, seg_acc = 0.f, iou_acc = 0.f;
    int cnt = 0;

    for (int i = 0; i < CH / 8; ++i) {   // 16 anchors per warp
        int a = warp * (CH / 8) + i;
        long long bn = (long long)b * NN + n0 + a;
        float gv  = grids[bn];
        float ps1 = psegs[bn * 3 + 1];
        float ps2 = psegs[bn * 3 + 2];
        if (lane == 0) {
            float vf = mask[bn] ? 0.f : 1.f;
            s_v[a] = vf;
            s_w[a] = vf * (0.75f * 0.69314718055994531f);
        }
        bool pos = inb && (gv > s_g) && (gv < e_g);
        if (pos) {
            cnt++;
            // smooth-L1 on log offsets (offsets strictly positive here)
            float d1 = ps1 - __logf(gv - s_g);
            float d2 = ps2 - __logf(e_g - gv);
            float a1 = fabsf(d1), a2 = fabsf(d2);
            seg_acc += (a1 < 1.f ? 0.5f * d1 * d1 : a1 - 0.5f)
                     + (a2 < 1.f ? 0.5f * d2 * d2 : a2 - 0.5f);
            // IoU of decoded segment vs GT
            float pls = gv - __expf(ps1);
            float ple = gv + __expf(ps2);
            float inter = fmaxf(fminf(ple, e_g) - fmaxf(pls, s_g), 0.f);
            float uni   = (ple - pls) + len_g - inter;
            iou_acc += 1.f - __fdividef(inter, uni);
            // union of matched classes (dedup via OR)
            atomicOr(&s_tgt[a * 8 + (lbl >> 5)], 1u << (lbl & 31));
        }
    }
    __syncthreads();

    // ---------------- Phase B: dense t=0 focal streaming ------------------
    // Block covers 128 contiguous anchor rows of 200 floats = 6400 float4;
    // exactly QPT=25 quads per thread, compile-time trip count so ptxas can
    // front-batch loads (MLP) under the 36-reg cap.
    const float4* basep = (const float4*)(logits + ((size_t)b * NN + n0) * NC);
    float ceB0 = 0.f, ceB1 = 0.f;
    #pragma unroll
    for (int k = 0; k < QPT; ++k) {
        int q = tid + k * 256;
        float4 v = basep[q];
        float wA = s_w[q / 50];
        ceB0 += wA * (g0(v.x) + g0(v.z));
        ceB1 += wA * (g0(v.y) + g0(v.w));
    }
    ce_acc += ceB0 + ceB1;

    // ---------------- Phase C: sparse t=1 corrections ----------------------
    // For each set (anchor, class) bit: add fl1 - fl0.
    const float* rowbase = logits + ((size_t)b * NN + n0) * NC;
    #pragma unroll
    for (int kk = 0; kk < 4; ++kk) {
        int wq = tid + kk * 256;
        unsigned m = s_tgt[wq];
        if (m) {
            int a  = wq >> 3;
            int wi = wq & 7;
            float vf = s_v[a];
            const float* rp = rowbase + a * NC + wi * 32;
            do {
                int bp = __ffs(m) - 1; m &= m - 1;
                float x = rp[bp];
                float u = __expf(x);
                float s = 1.f + u;
                float r = __fdividef(1.f, s);     // 1-p
                float sp = __logf(s);             // softplus(x)
                float w = 1.f - r;                // p
                // fl1 = 0.25*(sp - x)*r^2 ; fl0 = 0.75*sp*w^2
                ce_acc += vf * (0.25f * (sp - x) * r * r - 0.75f * sp * w * w);
            } while (m);
        }
    }

    // ---------------- Reduction + last-block finalize ----------------------
    #pragma unroll
    for (int o = 16; o; o >>= 1) {
        ce_acc  += __shfl_xor_sync(0xffffffffu, ce_acc,  o);
        seg_acc += __shfl_xor_sync(0xffffffffu, seg_acc, o);
        iou_acc += __shfl_xor_sync(0xffffffffu, iou_acc, o);
        cnt     += __shfl_xor_sync(0xffffffffu, cnt,     o);
    }
    if (lane == 0) {
        s_red[warp]      = ce_acc;
        s_red[8 + warp]  = seg_acc;
        s_red[16 + warp] = iou_acc;
        s_redc[warp]     = cnt;
    }
    __syncthreads();
    if (tid == 0) {
        double ce = 0.0, sg = 0.0, io = 0.0; int c = 0;
        #pragma unroll
        for (int w = 0; w < 8; ++w) {
            ce += (double)s_red[w];
            sg += (double)s_red[8 + w];
            io += (double)s_red[16 + w];
            c  += s_redc[w];
        }
        atomicAdd(&g_acc[0], ce);
        atomicAdd(&g_acc[1], sg);
        atomicAdd(&g_acc[2], io);
        atomicAdd(&g_cnt, (unsigned)c);
        __threadfence();
        unsigned t = atomicAdd(&g_done, 1u);
        if (t == TOTAL_BLOCKS - 1) {
            // all other blocks' contributions are visible (fence before ticket)
            double np = (double)atomicAdd(&g_cnt, 0u);
            if (np < 1.0) np = 1.0;
            double a0 = atomicAdd(&g_acc[0], 0.0);
            double a1 = atomicAdd(&g_acc[1], 0.0);
            double a2 = atomicAdd(&g_acc[2], 0.0);
            out[0] = (float)(a0 / np);
            out[1] = (float)(a1 / np);
            out[2] = (float)(a2 / np);
            // reset for next graph replay
            g_acc[0] = 0.0; g_acc[1] = 0.0; g_acc[2] = 0.0;
            g_cnt = 0u; g_done = 0u;
        }
    }
}

extern "C" void kernel_launch(void* const* d_in, const int* in_sizes, int n_in,
                              void* d_out, int out_size) {
    const float*         logits = (const float*)d_in[0];
    const float*         psegs  = (const float*)d_in[1];
    const float*         grids  = (const float*)d_in[2];
    const float*         fps    = (const float*)d_in[3];
    const float*         gts    = (const float*)d_in[4];
    const int*           glab   = (const int*)d_in[5];
    const unsigned char* maskp  = (const unsigned char*)d_in[6];
    float* out = (float*)d_out;

    dim3 grid(NBX, NB);
    loss_fused<<<grid, 256>>>(logits, psegs, grids, fps, gts, glab, maskp, out);
    (void)in_sizes; (void)n_in; (void)out_size;
}

// round 5
// speedup vs baseline: 2.0822x; 1.0420x over previous
#include <cuda_runtime.h>

#define NB 4
#define NC 200
#define NG 32
#define NN 32256
#define CH 128                    // anchors per block
#define NBX (NN / CH)             // 252
#define TOTAL_BLOCKS (NB * NBX)   // 1008 -> single wave at 7 blocks/SM
#define QPT ((CH * 50) / 256)     // 25 quads per thread in phase B
#define NS 6                      // cp.async ring slabs (depth-5 in flight)

__device__ double g_acc[3];
__device__ unsigned g_cnt;
__device__ unsigned g_done;

__device__ __forceinline__ void cp16(unsigned saddr, const void* g) {
    asm volatile("cp.async.cg.shared.global [%0], [%1], 16;" :: "r"(saddr), "l"(g));
}
#define CP_COMMIT() asm volatile("cp.async.commit_group;")
#define CP_WAIT5()  asm volatile("cp.async.wait_group 5;")

// t=0 focal core in log2 units: lg2(1+e^x) * sigmoid(x)^2.
// Caller multiplies by valid * 0.75 * ln2.
__device__ __forceinline__ float g0(float x) {
    float u = __expf(x);
    float s = 1.f + u;
    float r = __fdividef(1.f, s);
    float lg = __log2f(s);
    float w = 1.f - r;
    return lg * w * w;
}

__global__ void __launch_bounds__(256, 7)
loss_fused(const float* __restrict__ logits,        // [B,N,C]
           const float* __restrict__ psegs,         // [B,N,3]
           const float* __restrict__ grids,         // [B,N]
           const float* __restrict__ fps,           // [B]
           const float* __restrict__ gts,           // [B,G,2]
           const int*   __restrict__ glab,          // [B,G]
           const unsigned char* __restrict__ mask,  // [B,N]
           float* __restrict__ out)                 // [3]
{
    __shared__ float4   s_buf[NS][256];  // 24KB async staging ring
    __shared__ unsigned s_tgt[CH * 8];   // 224-bit class-target mask per anchor
    __shared__ float    s_w[CH];         // valid * 0.75 * ln2
    __shared__ float    s_v[CH];         // valid
    __shared__ float    s_red[3 * 8];
    __shared__ int      s_redc[8];

    const int tid  = threadIdx.x;
    const int lane = tid & 31;
    const int warp = tid >> 5;
    const int b    = blockIdx.y;
    const int n0   = blockIdx.x * CH;

    const float4* basep = (const float4*)(logits + ((size_t)b * NN + n0) * NC);
    unsigned sbase = (unsigned)__cvta_generic_to_shared(&s_buf[0][0]) + tid * 16u;

    // Kick off DRAM stream immediately: prologue slabs 0..NS-2 (one group each)
    #pragma unroll
    for (int j = 0; j < NS - 1; ++j) {
        cp16(sbase + j * 4096u, basep + tid + j * 256);
        CP_COMMIT();
    }

    #pragma unroll
    for (int k = 0; k < 4; ++k) s_tgt[tid + k * 256] = 0u;
    __syncthreads();

    // ---------------- Phase A: matching + seg/IoU + target masks ----------
    float2 seg  = ((const float2*)gts)[b * NG + lane];
    float s_g   = seg.x, e_g = seg.y;
    float len_g = e_g - s_g;
    int   lbl   = glab[b * NG + lane];
    float Cm    = 3.0f * fps[b] * 1.41421356237309515f;  // 3*fps*sqrt(2)

    int lvl = (n0 >= 16384) + (n0 >= 24576) + (n0 >= 28672) + (n0 >= 30720) + (n0 >= 31744);
    float lo = (lvl == 0) ? 0.f : Cm * exp2f((float)(lvl - 1));
    float hi = (lvl == 5) ? __int_as_float(0x7f800000) : Cm * exp2f((float)lvl);
    bool inb = (len_g >= lo) && (len_g < hi);

    float ce_acc = 0.f, seg_acc = 0.f, iou_acc = 0.f;
    int cnt = 0;

    for (int i = 0; i < CH / 8; ++i) {   // 16 anchors per warp
        int a = warp * (CH / 8) + i;
        long long bn = (long long)b * NN + n0 + a;
        float gv  = grids[bn];
        float ps1 = psegs[bn * 3 + 1];
        float ps2 = psegs[bn * 3 + 2];
        if (lane == 0) {
            float vf = mask[bn] ? 0.f : 1.f;
            s_v[a] = vf;
            s_w[a] = vf * (0.75f * 0.69314718055994531f);
        }
        bool pos = inb && (gv > s_g) && (gv < e_g);
        if (pos) {
            cnt++;
            float d1 = ps1 - __logf(gv - s_g);
            float d2 = ps2 - __logf(e_g - gv);
            float a1 = fabsf(d1), a2 = fabsf(d2);
            seg_acc += (a1 < 1.f ? 0.5f * d1 * d1 : a1 - 0.5f)
                     + (a2 < 1.f ? 0.5f * d2 * d2 : a2 - 0.5f);
            float pls = gv - __expf(ps1);
            float ple = gv + __expf(ps2);
            float inter = fmaxf(fminf(ple, e_g) - fmaxf(pls, s_g), 0.f);
            float uni   = (ple - pls) + len_g - inter;
            iou_acc += 1.f - __fdividef(inter, uni);
            atomicOr(&s_tgt[a * 8 + (lbl >> 5)], 1u << (lbl & 31));
        }
    }
    __syncthreads();

    // ---------------- Phase B: cp.async-pipelined t=0 focal stream ---------
    // Each thread consumes exactly the 16B it loaded -> no barriers needed:
    // cp.async -> commit -> wait_group 5 -> ld.shared.v4 is self-ordered.
    float ceB0 = 0.f, ceB1 = 0.f;
    #pragma unroll
    for (int k = 0; k < QPT; ++k) {
        int kn = k + NS - 1;
        if (kn < QPT) cp16(sbase + (kn % NS) * 4096u, basep + tid + kn * 256);
        CP_COMMIT();
        CP_WAIT5();
        float4 v = s_buf[k % NS][tid];
        int q = tid + k * 256;
        float wA = s_w[q / 50];
        ceB0 += wA * (g0(v.x) + g0(v.z));
        ceB1 += wA * (g0(v.y) + g0(v.w));
    }
    ce_acc += ceB0 + ceB1;

    // ---------------- Phase C: sparse t=1 corrections ----------------------
    const float* rowbase = logits + ((size_t)b * NN + n0) * NC;
    #pragma unroll
    for (int kk = 0; kk < 4; ++kk) {
        int wq = tid + kk * 256;
        unsigned m = s_tgt[wq];
        if (m) {
            int a  = wq >> 3;
            int wi = wq & 7;
            float vf = s_v[a];
            const float* rp = rowbase + a * NC + wi * 32;
            do {
                int bp = __ffs(m) - 1; m &= m - 1;
                float x = rp[bp];
                float u = __expf(x);
                float s = 1.f + u;
                float r = __fdividef(1.f, s);     // 1-p
                float sp = __logf(s);             // softplus(x)
                float w = 1.f - r;                // p
                ce_acc += vf * (0.25f * (sp - x) * r * r - 0.75f * sp * w * w);
            } while (m);
        }
    }

    // ---------------- Reduction + last-block finalize ----------------------
    #pragma unroll
    for (int o = 16; o; o >>= 1) {
        ce_acc  += __shfl_xor_sync(0xffffffffu, ce_acc,  o);
        seg_acc += __shfl_xor_sync(0xffffffffu, seg_acc, o);
        iou_acc += __shfl_xor_sync(0xffffffffu, iou_acc, o);
        cnt     += __shfl_xor_sync(0xffffffffu, cnt,     o);
    }
    if (lane == 0) {
        s_red[warp]      = ce_acc;
        s_red[8 + warp]  = seg_acc;
        s_red[16 + warp] = iou_acc;
        s_redc[warp]     = cnt;
    }
    __syncthreads();
    if (tid == 0) {
        double ce = 0.0, sg = 0.0, io = 0.0; int c = 0;
        #pragma unroll
        for (int w = 0; w < 8; ++w) {
            ce += (double)s_red[w];
            sg += (double)s_red[8 + w];
            io += (double)s_red[16 + w];
            c  += s_redc[w];
        }
        atomicAdd(&g_acc[0], ce);
        atomicAdd(&g_acc[1], sg);
        atomicAdd(&g_acc[2], io);
        atomicAdd(&g_cnt, (unsigned)c);
        __threadfence();
        unsigned t = atomicAdd(&g_done, 1u);
        if (t == TOTAL_BLOCKS - 1) {
            double np = (double)atomicAdd(&g_cnt, 0u);
            if (np < 1.0) np = 1.0;
            double a0 = atomicAdd(&g_acc[0], 0.0);
            double a1 = atomicAdd(&g_acc[1], 0.0);
            double a2 = atomicAdd(&g_acc[2], 0.0);
            out[0] = (float)(a0 / np);
            out[1] = (float)(a1 / np);
            out[2] = (float)(a2 / np);
            g_acc[0] = 0.0; g_acc[1] = 0.0; g_acc[2] = 0.0;
            g_cnt = 0u; g_done = 0u;
        }
    }
}

extern "C" void kernel_launch(void* const* d_in, const int* in_sizes, int n_in,
                              void* d_out, int out_size) {
    const float*         logits = (const float*)d_in[0];
    const float*         psegs  = (const float*)d_in[1];
    const float*         grids  = (const float*)d_in[2];
    const float*         fps    = (const float*)d_in[3];
    const float*         gts    = (const float*)d_in[4];
    const int*           glab   = (const int*)d_in[5];
    const unsigned char* maskp  = (const unsigned char*)d_in[6];
    float* out = (float*)d_out;

    dim3 grid(NBX, NB);
    loss_fused<<<grid, 256>>>(logits, psegs, grids, fps, gts, glab, maskp, out);
    (void)in_sizes; (void)n_in; (void)out_size;
}